// round 15
// baseline (speedup 1.0000x reference)
#include <cuda_runtime.h>
#include <cstdint>
#include <math_constants.h>

#define N_MAX 65536
#define M_IND 1024
#define KNN 16
#define BUFCAP 128
#define SU_NB 32
#define SU_BLOCKS (SU_NB * (SU_NB + 1) / 2)   // 528

// Scratch (static device globals — no allocation allowed)
__device__ unsigned g_idx[N_MAX * KNN];
__device__ float    g_Su[M_IND * M_IND];

// ---------------------------------------------------------------------------
// Kernel 1: Su = Lu Lu^T. 32x32 tiles, 528 triangular blocks, 256 thr, 2x2.
// ---------------------------------------------------------------------------
__global__ void su_kernel(const float* __restrict__ raw) {
    __shared__ float At[32][33];
    __shared__ float Bt[32][33];
    int s = blockIdx.x;
    int bi = (int)((__fsqrt_rn(8.0f * (float)s + 1.0f) - 1.0f) * 0.5f);
    while ((bi + 1) * (bi + 2) / 2 <= s) bi++;
    while (bi * (bi + 1) / 2 > s) bi--;
    int bj = s - bi * (bi + 1) / 2;          // bj <= bi

    int tid = threadIdx.x;
    int tx = tid & 15, ty = tid >> 4;
    int lr = tid >> 3;                       // 0..31 row in tile
    int lc = (tid & 7) << 2;                 // k col group of 4
    int rA = bi * 32, rB = bj * 32;
    int nk = (bj + 1) * 32;                  // k <= min(i,j); rest is 0

    float acc00 = 0.f, acc01 = 0.f, acc10 = 0.f, acc11 = 0.f;
    for (int kc = 0; kc < nk; kc += 32) {
        int ga = rA + lr;
        float4 va = *(const float4*)(raw + (size_t)ga * M_IND + kc + lc);
        int gb = rB + lr;
        float4 vb = *(const float4*)(raw + (size_t)gb * M_IND + kc + lc);
        float a4[4] = {va.x, va.y, va.z, va.w};
        float b4[4] = {vb.x, vb.y, vb.z, vb.w};
#pragma unroll
        for (int u = 0; u < 4; u++) {
            int gc = kc + lc + u;
            float x = a4[u];
            At[lc + u][lr] = (gc < ga) ? x : ((gc == ga) ? expf(x) : 0.0f);
            float y = b4[u];
            Bt[lc + u][lr] = (gc < gb) ? y : ((gc == gb) ? expf(y) : 0.0f);
        }
        __syncthreads();
#pragma unroll
        for (int kk = 0; kk < 32; kk++) {
            float a0 = At[kk][ty * 2], a1 = At[kk][ty * 2 + 1];
            float b0 = Bt[kk][tx * 2], b1 = Bt[kk][tx * 2 + 1];
            acc00 = fmaf(a0, b0, acc00);
            acc01 = fmaf(a0, b1, acc01);
            acc10 = fmaf(a1, b0, acc10);
            acc11 = fmaf(a1, b1, acc11);
        }
        __syncthreads();
    }
    int gi0 = rA + ty * 2, gj0 = rB + tx * 2;
    g_Su[(size_t)gi0 * M_IND + gj0]           = acc00;
    g_Su[(size_t)gi0 * M_IND + gj0 + 1]       = acc01;
    g_Su[(size_t)(gi0 + 1) * M_IND + gj0]     = acc10;
    g_Su[(size_t)(gi0 + 1) * M_IND + gj0 + 1] = acc11;
    g_Su[(size_t)gj0 * M_IND + gi0]           = acc00;
    g_Su[(size_t)(gj0 + 1) * M_IND + gi0]     = acc01;
    g_Su[(size_t)gj0 * M_IND + gi0 + 1]       = acc10;
    g_Su[(size_t)(gj0 + 1) * M_IND + gi0 + 1] = acc11;
}

// ---------------------------------------------------------------------------
// Kernel 2: exact 16-NN, thread per point (E-space scans, single-pass P4).
// ---------------------------------------------------------------------------
__global__ void topk_kernel(const float* __restrict__ X,
                            const float* __restrict__ Z, int N) {
    __shared__ float4 zs[M_IND];
    for (int t = threadIdx.x; t < M_IND; t += blockDim.x) {
        float a = Z[3 * t], b = Z[3 * t + 1], c = Z[3 * t + 2];
        zs[t] = make_float4(a, b, c, fmaf(a, a, fmaf(b, b, c * c)));
    }
    __syncthreads();
    int p = blockIdx.x * blockDim.x + threadIdx.x;
    if (p >= N) return;
    float x0 = X[3 * p], x1 = X[3 * p + 1], x2 = X[3 * p + 2];
    float xs = fmaf(x0, x0, fmaf(x1, x1, x2 * x2));
    float n0 = -2.0f * x0, n1 = -2.0f * x1, n2 = -2.0f * x2;

#define EV(Zv)    fmaf(n2, (Zv).z, fmaf(n1, (Zv).y, fmaf(n0, (Zv).x, (Zv).w)))
#define DISTC(Zv) fmaxf(xs + EV(Zv), 0.0f)

    // ---- P1: full scan, 16 interleaved group-min chains over E ----
    float mins[16];
#pragma unroll
    for (int g = 0; g < 16; g++) mins[g] = CUDART_INF_F;
#pragma unroll 2
    for (int jj = 0; jj < 64; jj++) {
#pragma unroll
        for (int g = 0; g < 16; g++) {
            float4 z = zs[(g << 6) + jj];
            mins[g] = fminf(mins[g], EV(z));
        }
    }
    float te = mins[0];
#pragma unroll
    for (int g = 1; g < 16; g++) te = fmaxf(te, mins[g]);
    te = fmaxf(te, -xs);   // clamp-superset guarantee (raw <= 0 candidates)

    // ---- P2: predicated u16 buffering of {E <= te} ----
    unsigned short buf[BUFCAP];
    int c = 0;
    for (int i = 0; i < M_IND; i += 8) {
        int t[8];
#pragma unroll
        for (int u = 0; u < 8; u++) {
            float4 z = zs[i + u];
            t[u] = EV(z) <= te;
        }
        int s01 = t[0] + t[1], s23 = t[2] + t[3];
        int s45 = t[4] + t[5], s67 = t[6] + t[7];
        int s03 = s01 + s23;
        int pre[8];
        pre[0] = 0;         pre[1] = t[0];
        pre[2] = s01;       pre[3] = s01 + t[2];
        pre[4] = s03;       pre[5] = s03 + t[4];
        pre[6] = s03 + s45; pre[7] = s03 + s45 + t[6];
#pragma unroll
        for (int u = 0; u < 8; u++) {
            int w = c + pre[u];
            w = w < BUFCAP ? w : BUFCAP - 1;
            if (t[u]) buf[w] = (unsigned short)(i + u);
        }
        c += s03 + s45 + s67;
    }

    unsigned base = (unsigned)p * KNN;
    if (c <= BUFCAP) {
        // ---- P3: exact 16th among candidates (2-way interleaved bubble) ----
        float ks3[KNN];
#pragma unroll
        for (int s = 0; s < KNN; s++) ks3[s] = CUDART_INF_F;
        int c2 = c & ~1;
        for (int j = 0; j < c2; j += 2) {
            float4 za = zs[buf[j]], zb = zs[buf[j + 1]];
            float ta = DISTC(za), tb = DISTC(zb);
#pragma unroll
            for (int s = 0; s < KNN; s++) {
                float a = ks3[s];
                float m0 = fminf(a, ta);  ta = fmaxf(a, ta);
                float m1 = fminf(m0, tb); tb = fmaxf(m0, tb);
                ks3[s] = m1;
            }
        }
        if (c & 1) {
            float4 za = zs[buf[c - 1]];
            float ta = DISTC(za);
#pragma unroll
            for (int s = 0; s < KNN; s++) {
                float a = ks3[s];
                ks3[s] = fminf(a, ta); ta = fmaxf(a, ta);
            }
        }
        float Tstar = ks3[KNN - 1];

        // nLess = #candidates strictly below T* (from P3 registers; <= 15)
        int nLess = 0;
#pragma unroll
        for (int s = 0; s < KNN; s++) nLess += (ks3[s] < Tstar) ? 1 : 0;

        // ---- P4: single-pass emission (stricts at cntL, ties at nLess+cntT)
        int cntL = 0, cntT = 0;
        for (int j = 0; j < c; j++) {
            int i = buf[j];
            float4 z = zs[i];
            float dd = DISTC(z);
            bool e1 = (dd < Tstar);
            bool e2 = (dd == Tstar) & (nLess + cntT < KNN);
            int slot = e1 ? cntL : (nLess + cntT);
            if (e1 | e2) g_idx[base + slot] = (unsigned)i;
            cntL += e1;
            cntT += e2;
        }
    } else {
        // Fallback: full exact u64 replace-max (pathological only)
        unsigned long long ks2[KNN];
#pragma unroll
        for (int s = 0; s < KNN; s++)
            ks2[s] = 0xFFFFFFFF00000000ull | (unsigned)s;
        unsigned long long kmax2 = 0xFFFFFFFF0000000Full;
        for (int i = 0; i < M_IND; i++) {
            float4 z = zs[i];
            float dd = DISTC(z);
            unsigned long long key =
                ((unsigned long long)__float_as_uint(dd) << 32) | (unsigned)i;
            if (key < kmax2) {
#pragma unroll
                for (int s = 0; s < KNN; s++) ks2[s] = (ks2[s] == kmax2) ? key : ks2[s];
                unsigned long long m = ks2[0];
#pragma unroll
                for (int s = 1; s < KNN; s++) m = max(m, ks2[s]);
                kmax2 = m;
            }
        }
#pragma unroll
        for (int s = 0; s < KNN; s++)
            g_idx[base + s] = (unsigned)(ks2[s] & 0xFFFFFFFFu);
    }
#undef EV
#undef DISTC
}

// ---------------------------------------------------------------------------
// Kernel 3: half-warp per point, register fp32 Gauss-Jordan; symmetric cov.
// ---------------------------------------------------------------------------
__global__ void solve_kernel(const float* __restrict__ X,
                             const float* __restrict__ Z,
                             const float* __restrict__ mu,
                             float* __restrict__ out, int N) {
    const unsigned FULL = 0xFFFFFFFFu;
    int lane = threadIdx.x & 31;
    int half = lane >> 4;
    int l = lane & 15;
    int p = (blockIdx.x << 4) + ((threadIdx.x >> 5) << 1) + half;
    int pc = p < N ? p : N - 1;

    float x0 = X[3 * pc], x1 = X[3 * pc + 1], x2 = X[3 * pc + 2];
    float xs = fmaf(x0, x0, fmaf(x1, x1, x2 * x2));

    unsigned idxv = g_idx[(size_t)pc * KNN + l];
    float zx = Z[3 * idxv], zy = Z[3 * idxv + 1], zz = Z[3 * idxv + 2];
    float z2 = fmaf(zx, zx, fmaf(zy, zy, zz * zz));
    float d2r = fmaxf(xs + z2 - 2.0f * fmaf(x0, zx, fmaf(x1, zy, x2 * zz)), 0.0f);
    float muv = mu[idxv];

    float a[17];
    float kz[16];                // pre-GJ kernel column (lKzz[i][l]), reused in cov
    a[16] = expf(-0.5f * d2r);   // rhs = lKxz

#pragma unroll
    for (int i = 0; i < 16; i++) {
        float zxi = __shfl_sync(FULL, zx, i, 16);
        float zyi = __shfl_sync(FULL, zy, i, 16);
        float zzi = __shfl_sync(FULL, zz, i, 16);
        float dx = zxi - zx, dy = zyi - zy, dz = zzi - zz;
        float d2 = fmaf(dx, dx, fmaf(dy, dy, dz * dz));
        float v = (i == l) ? (1.0f + 2e-4f) : expf(-0.5f * d2);
        a[i] = v;
        kz[i] = v;
    }

#pragma unroll
    for (int k = 0; k < 16; k++) {
        float piv = __shfl_sync(FULL, a[k], k, 16);
        float rp = 1.0f / piv;
        float f = (l == k) ? 0.0f : a[k] * rp;
#pragma unroll
        for (int cc = k + 1; cc <= 16; cc++) {
            float bc = __shfl_sync(FULL, a[cc], k, 16);
            a[cc] = fmaf(-f, bc, a[cc]);
        }
    }
    float diag = a[0];
#pragma unroll
    for (int cc = 1; cc < 16; cc++) if (l == cc) diag = a[cc];
    float Wv = a[16] / diag;

    // cov = 1 + Wv^2 (su_ll - (1+1e-4)) + 2 * sum_{i<l} Wi Wv (su_il - kz[i])
    float acc = 0.0f;
#pragma unroll
    for (int i = 0; i < 15; i++) {
        float Wi = __shfl_sync(FULL, Wv, i, 16);
        unsigned ia = __shfl_sync(FULL, idxv, i, 16);
        bool keep = (i < l);
        const float* addr = keep ? (g_Su + (size_t)ia * M_IND + idxv) : g_Su;
        float su = __ldg(addr);
        float coef = keep ? 2.0f * Wi * Wv : 0.0f;
        acc = fmaf(coef, su - kz[i], acc);
    }
    {
        float su_ll = __ldg(g_Su + (size_t)idxv * M_IND + idxv);
        acc = fmaf(Wv * Wv, su_ll - 1.0001f, acc);
    }
    float mpart = Wv * muv;
#pragma unroll
    for (int o = 8; o > 0; o >>= 1) {
        acc   += __shfl_xor_sync(FULL, acc, o, 16);
        mpart += __shfl_xor_sync(FULL, mpart, o, 16);
    }
    if (l == 0 && p < N) {
        out[p] = mpart;                                // mean
        float cov = 1.0f + acc;
        out[N + p] = sqrtf(fmaxf(cov, 0.05f));         // std
    }
}

// ---------------------------------------------------------------------------
// Launch: fork su onto a side stream so it overlaps topk (topk occ is 18% --
// plenty of idle warp slots). Canonical capture-safe fork/join via events.
// Streams/events are host objects (no device memory); created fresh per call.
// ---------------------------------------------------------------------------
extern "C" void kernel_launch(void* const* d_in, const int* in_sizes, int n_in,
                              void* d_out, int out_size) {
    const float* X      = (const float*)d_in[0];
    const float* Z      = (const float*)d_in[1];
    const float* Lu_raw = (const float*)d_in[2];
    const float* mu     = (const float*)d_in[3];
    float* out = (float*)d_out;
    int N = in_sizes[0] / 3;

    cudaStream_t s2;
    cudaEvent_t eFork, eJoin;
    cudaStreamCreateWithFlags(&s2, cudaStreamNonBlocking);
    cudaEventCreateWithFlags(&eFork, cudaEventDisableTiming);
    cudaEventCreateWithFlags(&eJoin, cudaEventDisableTiming);

    // fork: side stream inherits capture dependency from origin stream
    cudaEventRecord(eFork, 0);
    cudaStreamWaitEvent(s2, eFork, 0);

    su_kernel<<<SU_BLOCKS, 256, 0, s2>>>(Lu_raw);          // side stream
    topk_kernel<<<(N + 127) / 128, 128>>>(X, Z, N);        // origin stream

    // join: solve depends on both su (g_Su) and topk (g_idx)
    cudaEventRecord(eJoin, s2);
    cudaStreamWaitEvent(0, eJoin, 0);

    solve_kernel<<<(N + 15) / 16, 256>>>(X, Z, mu, out, N);
}

// round 17
// speedup vs baseline: 1.9834x; 1.9834x over previous
#include <cuda_runtime.h>
#include <cstdint>
#include <math_constants.h>

#define N_MAX 65536
#define M_IND 1024
#define KNN 16
#define BUFCAP 128
#define SU_NB 32
#define SU_BLOCKS (SU_NB * (SU_NB + 1) / 2)   // 528

// Scratch (static device globals — no allocation allowed)
__device__ unsigned g_idx[N_MAX * KNN];
__device__ float    g_Su[M_IND * M_IND];

// ---------------------------------------------------------------------------
// Kernel 1: Su = Lu Lu^T. 32x32 tiles, 528 triangular blocks, 256 thr, 2x2.
// ---------------------------------------------------------------------------
__global__ void su_kernel(const float* __restrict__ raw) {
    __shared__ float At[32][33];
    __shared__ float Bt[32][33];
    int s = blockIdx.x;
    int bi = (int)((__fsqrt_rn(8.0f * (float)s + 1.0f) - 1.0f) * 0.5f);
    while ((bi + 1) * (bi + 2) / 2 <= s) bi++;
    while (bi * (bi + 1) / 2 > s) bi--;
    int bj = s - bi * (bi + 1) / 2;          // bj <= bi

    int tid = threadIdx.x;
    int tx = tid & 15, ty = tid >> 4;
    int lr = tid >> 3;                       // 0..31 row in tile
    int lc = (tid & 7) << 2;                 // k col group of 4
    int rA = bi * 32, rB = bj * 32;
    int nk = (bj + 1) * 32;                  // k <= min(i,j); rest is 0

    float acc00 = 0.f, acc01 = 0.f, acc10 = 0.f, acc11 = 0.f;
    for (int kc = 0; kc < nk; kc += 32) {
        int ga = rA + lr;
        float4 va = *(const float4*)(raw + (size_t)ga * M_IND + kc + lc);
        int gb = rB + lr;
        float4 vb = *(const float4*)(raw + (size_t)gb * M_IND + kc + lc);
        float a4[4] = {va.x, va.y, va.z, va.w};
        float b4[4] = {vb.x, vb.y, vb.z, vb.w};
#pragma unroll
        for (int u = 0; u < 4; u++) {
            int gc = kc + lc + u;
            float x = a4[u];
            At[lc + u][lr] = (gc < ga) ? x : ((gc == ga) ? expf(x) : 0.0f);
            float y = b4[u];
            Bt[lc + u][lr] = (gc < gb) ? y : ((gc == gb) ? expf(y) : 0.0f);
        }
        __syncthreads();
#pragma unroll
        for (int kk = 0; kk < 32; kk++) {
            float a0 = At[kk][ty * 2], a1 = At[kk][ty * 2 + 1];
            float b0 = Bt[kk][tx * 2], b1 = Bt[kk][tx * 2 + 1];
            acc00 = fmaf(a0, b0, acc00);
            acc01 = fmaf(a0, b1, acc01);
            acc10 = fmaf(a1, b0, acc10);
            acc11 = fmaf(a1, b1, acc11);
        }
        __syncthreads();
    }
    int gi0 = rA + ty * 2, gj0 = rB + tx * 2;
    g_Su[(size_t)gi0 * M_IND + gj0]           = acc00;
    g_Su[(size_t)gi0 * M_IND + gj0 + 1]       = acc01;
    g_Su[(size_t)(gi0 + 1) * M_IND + gj0]     = acc10;
    g_Su[(size_t)(gi0 + 1) * M_IND + gj0 + 1] = acc11;
    g_Su[(size_t)gj0 * M_IND + gi0]           = acc00;
    g_Su[(size_t)(gj0 + 1) * M_IND + gi0]     = acc01;
    g_Su[(size_t)gj0 * M_IND + gi0 + 1]       = acc10;
    g_Su[(size_t)(gj0 + 1) * M_IND + gi0 + 1] = acc11;
}

// ---------------------------------------------------------------------------
// Kernel 2: exact 16-NN, thread per point (E-space scans, single-pass P4).
// ---------------------------------------------------------------------------
__global__ void topk_kernel(const float* __restrict__ X,
                            const float* __restrict__ Z, int N) {
    __shared__ float4 zs[M_IND];
    for (int t = threadIdx.x; t < M_IND; t += blockDim.x) {
        float a = Z[3 * t], b = Z[3 * t + 1], c = Z[3 * t + 2];
        zs[t] = make_float4(a, b, c, fmaf(a, a, fmaf(b, b, c * c)));
    }
    __syncthreads();
    int p = blockIdx.x * blockDim.x + threadIdx.x;
    if (p >= N) return;
    float x0 = X[3 * p], x1 = X[3 * p + 1], x2 = X[3 * p + 2];
    float xs = fmaf(x0, x0, fmaf(x1, x1, x2 * x2));
    float n0 = -2.0f * x0, n1 = -2.0f * x1, n2 = -2.0f * x2;

#define EV(Zv)    fmaf(n2, (Zv).z, fmaf(n1, (Zv).y, fmaf(n0, (Zv).x, (Zv).w)))
#define DISTC(Zv) fmaxf(xs + EV(Zv), 0.0f)

    // ---- P1: full scan, 16 interleaved group-min chains over E ----
    float mins[16];
#pragma unroll
    for (int g = 0; g < 16; g++) mins[g] = CUDART_INF_F;
#pragma unroll 2
    for (int jj = 0; jj < 64; jj++) {
#pragma unroll
        for (int g = 0; g < 16; g++) {
            float4 z = zs[(g << 6) + jj];
            mins[g] = fminf(mins[g], EV(z));
        }
    }
    float te = mins[0];
#pragma unroll
    for (int g = 1; g < 16; g++) te = fmaxf(te, mins[g]);
    te = fmaxf(te, -xs);   // clamp-superset guarantee (raw <= 0 candidates)

    // ---- P2: predicated u16 buffering of {E <= te} ----
    unsigned short buf[BUFCAP];
    int c = 0;
    for (int i = 0; i < M_IND; i += 8) {
        int t[8];
#pragma unroll
        for (int u = 0; u < 8; u++) {
            float4 z = zs[i + u];
            t[u] = EV(z) <= te;
        }
        int s01 = t[0] + t[1], s23 = t[2] + t[3];
        int s45 = t[4] + t[5], s67 = t[6] + t[7];
        int s03 = s01 + s23;
        int pre[8];
        pre[0] = 0;         pre[1] = t[0];
        pre[2] = s01;       pre[3] = s01 + t[2];
        pre[4] = s03;       pre[5] = s03 + t[4];
        pre[6] = s03 + s45; pre[7] = s03 + s45 + t[6];
#pragma unroll
        for (int u = 0; u < 8; u++) {
            int w = c + pre[u];
            w = w < BUFCAP ? w : BUFCAP - 1;
            if (t[u]) buf[w] = (unsigned short)(i + u);
        }
        c += s03 + s45 + s67;
    }

    unsigned base = (unsigned)p * KNN;
    if (c <= BUFCAP) {
        // ---- P3: exact 16th among candidates (2-way interleaved bubble) ----
        float ks3[KNN];
#pragma unroll
        for (int s = 0; s < KNN; s++) ks3[s] = CUDART_INF_F;
        int c2 = c & ~1;
        for (int j = 0; j < c2; j += 2) {
            float4 za = zs[buf[j]], zb = zs[buf[j + 1]];
            float ta = DISTC(za), tb = DISTC(zb);
#pragma unroll
            for (int s = 0; s < KNN; s++) {
                float a = ks3[s];
                float m0 = fminf(a, ta);  ta = fmaxf(a, ta);
                float m1 = fminf(m0, tb); tb = fmaxf(m0, tb);
                ks3[s] = m1;
            }
        }
        if (c & 1) {
            float4 za = zs[buf[c - 1]];
            float ta = DISTC(za);
#pragma unroll
            for (int s = 0; s < KNN; s++) {
                float a = ks3[s];
                ks3[s] = fminf(a, ta); ta = fmaxf(a, ta);
            }
        }
        float Tstar = ks3[KNN - 1];

        // nLess = #candidates strictly below T* (from P3 registers; <= 15)
        int nLess = 0;
#pragma unroll
        for (int s = 0; s < KNN; s++) nLess += (ks3[s] < Tstar) ? 1 : 0;

        // ---- P4: single-pass emission (stricts at cntL, ties at nLess+cntT)
        int cntL = 0, cntT = 0;
        for (int j = 0; j < c; j++) {
            int i = buf[j];
            float4 z = zs[i];
            float dd = DISTC(z);
            bool e1 = (dd < Tstar);
            bool e2 = (dd == Tstar) & (nLess + cntT < KNN);
            int slot = e1 ? cntL : (nLess + cntT);
            if (e1 | e2) g_idx[base + slot] = (unsigned)i;
            cntL += e1;
            cntT += e2;
        }
    } else {
        // Fallback: full exact u64 replace-max (pathological only)
        unsigned long long ks2[KNN];
#pragma unroll
        for (int s = 0; s < KNN; s++)
            ks2[s] = 0xFFFFFFFF00000000ull | (unsigned)s;
        unsigned long long kmax2 = 0xFFFFFFFF0000000Full;
        for (int i = 0; i < M_IND; i++) {
            float4 z = zs[i];
            float dd = DISTC(z);
            unsigned long long key =
                ((unsigned long long)__float_as_uint(dd) << 32) | (unsigned)i;
            if (key < kmax2) {
#pragma unroll
                for (int s = 0; s < KNN; s++) ks2[s] = (ks2[s] == kmax2) ? key : ks2[s];
                unsigned long long m = ks2[0];
#pragma unroll
                for (int s = 1; s < KNN; s++) m = max(m, ks2[s]);
                kmax2 = m;
            }
        }
#pragma unroll
        for (int s = 0; s < KNN; s++)
            g_idx[base + s] = (unsigned)(ks2[s] & 0xFFFFFFFFu);
    }
#undef EV
#undef DISTC
}

// ---------------------------------------------------------------------------
// Kernel 3: half-warp per point, register fp32 Gauss-Jordan; symmetric cov.
// Pre-GJ kernel column kz[] cached in registers -> cov loop needs no exp.
// ---------------------------------------------------------------------------
__global__ void solve_kernel(const float* __restrict__ X,
                             const float* __restrict__ Z,
                             const float* __restrict__ mu,
                             float* __restrict__ out, int N) {
    const unsigned FULL = 0xFFFFFFFFu;
    int lane = threadIdx.x & 31;
    int half = lane >> 4;
    int l = lane & 15;
    int p = (blockIdx.x << 4) + ((threadIdx.x >> 5) << 1) + half;
    int pc = p < N ? p : N - 1;

    float x0 = X[3 * pc], x1 = X[3 * pc + 1], x2 = X[3 * pc + 2];
    float xs = fmaf(x0, x0, fmaf(x1, x1, x2 * x2));

    unsigned idxv = g_idx[(size_t)pc * KNN + l];
    float zx = Z[3 * idxv], zy = Z[3 * idxv + 1], zz = Z[3 * idxv + 2];
    float z2 = fmaf(zx, zx, fmaf(zy, zy, zz * zz));
    float d2r = fmaxf(xs + z2 - 2.0f * fmaf(x0, zx, fmaf(x1, zy, x2 * zz)), 0.0f);
    float muv = mu[idxv];

    float a[17];
    float kz[16];                // pre-GJ kernel column (lKzz[i][l]), reused in cov
    a[16] = expf(-0.5f * d2r);   // rhs = lKxz

#pragma unroll
    for (int i = 0; i < 16; i++) {
        float zxi = __shfl_sync(FULL, zx, i, 16);
        float zyi = __shfl_sync(FULL, zy, i, 16);
        float zzi = __shfl_sync(FULL, zz, i, 16);
        float dx = zxi - zx, dy = zyi - zy, dz = zzi - zz;
        float d2 = fmaf(dx, dx, fmaf(dy, dy, dz * dz));
        float v = (i == l) ? (1.0f + 2e-4f) : expf(-0.5f * d2);
        a[i] = v;
        kz[i] = v;
    }

#pragma unroll
    for (int k = 0; k < 16; k++) {
        float piv = __shfl_sync(FULL, a[k], k, 16);
        float rp = 1.0f / piv;
        float f = (l == k) ? 0.0f : a[k] * rp;
#pragma unroll
        for (int cc = k + 1; cc <= 16; cc++) {
            float bc = __shfl_sync(FULL, a[cc], k, 16);
            a[cc] = fmaf(-f, bc, a[cc]);
        }
    }
    float diag = a[0];
#pragma unroll
    for (int cc = 1; cc < 16; cc++) if (l == cc) diag = a[cc];
    float Wv = a[16] / diag;

    // cov = 1 + Wv^2 (su_ll - (1+1e-4)) + 2 * sum_{i<l} Wi Wv (su_il - kz[i])
    float acc = 0.0f;
#pragma unroll
    for (int i = 0; i < 15; i++) {
        float Wi = __shfl_sync(FULL, Wv, i, 16);
        unsigned ia = __shfl_sync(FULL, idxv, i, 16);
        bool keep = (i < l);
        const float* addr = keep ? (g_Su + (size_t)ia * M_IND + idxv) : g_Su;
        float su = __ldg(addr);
        float coef = keep ? 2.0f * Wi * Wv : 0.0f;
        acc = fmaf(coef, su - kz[i], acc);
    }
    {
        float su_ll = __ldg(g_Su + (size_t)idxv * M_IND + idxv);
        acc = fmaf(Wv * Wv, su_ll - 1.0001f, acc);
    }
    float mpart = Wv * muv;
#pragma unroll
    for (int o = 8; o > 0; o >>= 1) {
        acc   += __shfl_xor_sync(FULL, acc, o, 16);
        mpart += __shfl_xor_sync(FULL, mpart, o, 16);
    }
    if (l == 0 && p < N) {
        out[p] = mpart;                                // mean
        float cov = 1.0f + acc;
        out[N + p] = sqrtf(fmaxf(cov, 0.05f));         // std
    }
}

// ---------------------------------------------------------------------------
extern "C" void kernel_launch(void* const* d_in, const int* in_sizes, int n_in,
                              void* d_out, int out_size) {
    const float* X      = (const float*)d_in[0];
    const float* Z      = (const float*)d_in[1];
    const float* Lu_raw = (const float*)d_in[2];
    const float* mu     = (const float*)d_in[3];
    float* out = (float*)d_out;
    int N = in_sizes[0] / 3;

    topk_kernel<<<(N + 127) / 128, 128>>>(X, Z, N);
    su_kernel<<<SU_BLOCKS, 256>>>(Lu_raw);
    solve_kernel<<<(N + 15) / 16, 256>>>(X, Z, mu, out, N);
}